// round 17
// baseline (speedup 1.0000x reference)
#include <cuda_runtime.h>
#include <cuda_fp16.h>
#include <cstdint>

// LogicalConsistencyLoss: out = sum_{s,a,b,c} relu(M_ab - M_ac*M_bc) / (R*B)
// where M = fp16(sigmoid(logits)) * mask_a * mask_b per (batch,relation) slice.
// R17: single PERSISTENT kernel (444 CTAs = 3/SM, co-resident by construction):
//   phase 1 = grid-strided sigmoid+mask (R16 body, bit-identical math)
//   device barrier (arrive + tid0 spin w/ nanosleep)
//   phase 2 = static tile loop over 2048 cubic tiles (confirmed R12 body)
//   last-CTA fused final reduce; counters reset for graph replay.

#define B_ 2
#define N_ 512
#define R_ 4
#define S_ (B_ * R_)                   // 8 slices
#define NT (N_ / 128)                  // 4 tiles per dim
#define CS 16                          // c-split: 32 c's per CTA-tile
#define NTILE (NT * NT * CS * S_)      // 2048 cubic tiles / partials
#define PCTA 444                       // persistent CTAs (148 SMs x 3)

__device__ __half    g_relh[S_ * N_ * N_];   // 4 MB scratch (L2-resident)
__device__ float     g_part[NTILE];
__device__ unsigned  g_bar1;                 // phase-1 barrier (zero-init)
__device__ unsigned  g_ctr;                  // completion counter (zero-init)

__global__ void __launch_bounds__(256, 3)
fused_kernel(const float* __restrict__ logits,
             const int*   __restrict__ masks,
             float* __restrict__ out) {
    const int tid = threadIdx.x;
    const int tx  = tid & 15;         // b sub-tile
    const int ty  = tid >> 4;         // a sub-tile

    __shared__ __align__(16) __half sA[32][256];   // 16 KB
    __shared__ __align__(16) __half sB[32][128];   //  8 KB
    float*  wred  = reinterpret_cast<float*>(&sA[0][0]);   // 8 floats (aliased)
    double* dw    = reinterpret_cast<double*>(&sA[1][0]);  // 8 doubles
    int*    lastf = reinterpret_cast<int*>(&sA[2][0]);     // amLast flag

    // ---------------- Phase 1: sigmoid + mask -> fp16 (grid-strided) --------
    {
        const int J2  = N_ / 2;                       // 256 j-pairs per row
        const int TOT = B_ * N_ * J2;                 // 262144 units
        for (int t = blockIdx.x * 256 + tid; t < TOT; t += PCTA * 256) {
            int b   = t / (N_ * J2);
            int rem = t - b * (N_ * J2);
            int i   = rem / J2;
            int j0  = (rem - i * J2) * 2;

            float mi = (masks[b * N_ + i] > 0) ? 1.0f : 0.0f;
            const float4* src =
                (const float4*)logits + (b * N_ * N_ + i * N_ + j0);
            float4 v0 = src[0];
            float4 v1 = src[1];
            float m0 = (masks[b * N_ + j0]     > 0) ? mi : 0.0f;
            float m1 = (masks[b * N_ + j0 + 1] > 0) ? mi : 0.0f;

            __half2 h[4];
            h[0] = __halves2half2(
                __float2half(__fdividef(m0, 1.0f + __expf(-v0.x))),
                __float2half(__fdividef(m1, 1.0f + __expf(-v1.x))));
            h[1] = __halves2half2(
                __float2half(__fdividef(m0, 1.0f + __expf(-v0.y))),
                __float2half(__fdividef(m1, 1.0f + __expf(-v1.y))));
            h[2] = __halves2half2(
                __float2half(__fdividef(m0, 1.0f + __expf(-v0.z))),
                __float2half(__fdividef(m1, 1.0f + __expf(-v1.z))));
            h[3] = __halves2half2(
                __float2half(__fdividef(m0, 1.0f + __expf(-v0.w))),
                __float2half(__fdividef(m1, 1.0f + __expf(-v1.w))));
#pragma unroll
            for (int r = 0; r < 4; ++r)
                *(uint32_t*)(g_relh + (b * R_ + r) * N_ * N_ + i * N_ + j0) =
                    *(uint32_t*)&h[r];
        }
    }

    // ---------------- Device-wide barrier (all PCTA CTAs co-resident) -------
    __syncthreads();
    if (tid == 0) {
        __threadfence();                       // publish phase-1 stores
        atomicAdd(&g_bar1, 1u);
        while (*(volatile unsigned*)&g_bar1 < PCTA) __nanosleep(64);
        __threadfence();                       // acquire peers' stores
    }
    __syncthreads();

    // ---------------- Phase 2: cubic relu contraction (static tile loop) ----
    for (int tIdx = blockIdx.x; tIdx < NTILE; tIdx += PCTA) {
        const int sl   = tIdx >> 8;            // 0..7
        const int rem8 = tIdx & 255;
        const int cblk = rem8 >> 4;            // 0..15
        const int tile = rem8 & 15;            // 0..15
        const __half* __restrict__ M = g_relh + sl * N_ * N_;

        const int a0 = (tile / NT) * 128;
        const int b0 = (tile % NT) * 128;
        const int c0 = cblk * (N_ / CS);       // 32 c's per tile

        // 8x8 M_ab tile packed as half2 (j,j+1) pairs: 32 regs.
        __half2 mab2[8][4];
#pragma unroll
        for (int i = 0; i < 8; ++i) {
            uint4 q = *(const uint4*)(M + (a0 + ty * 8 + i) * N_ + b0 + tx * 8);
            mab2[i][0] = *(__half2*)&q.x; mab2[i][1] = *(__half2*)&q.y;
            mab2[i][2] = *(__half2*)&q.z; mab2[i][3] = *(__half2*)&q.w;
        }

        // Stage all 32 c's (sA negated+duplicated; sB transposed).
        {
            const int  sr  = tid & 127;
            const bool isB = tid >= 128;
            const __half* rowp = M + ((isB ? b0 : a0) + sr) * N_ + c0;
#pragma unroll
            for (int q = 0; q < 4; ++q) {
                uint4 v = ((const uint4*)rowp)[q];
                __half h[8];
                *(uint4*)&h[0] = v;
                const int cbase = 8 * q;
                if (!isB) {
#pragma unroll
                    for (int k = 0; k < 8; ++k) {
                        __half2 p = __half2half2(__hneg(h[k]));
                        *(uint32_t*)&sA[cbase + k][2 * sr] = *(uint32_t*)&p;
                    }
                } else {
#pragma unroll
                    for (int k = 0; k < 8; ++k) sB[cbase + k][sr] = h[k];
                }
            }
        }
        __syncthreads();

        float facc[2] = {0.0f, 0.0f};

#pragma unroll
        for (int cb = 0; cb < 32; cb += 8) {
            __half2 hacc[8];                   // per-i accs: <=32 terms each
#pragma unroll
            for (int i = 0; i < 8; ++i) hacc[i] = __float2half2_rn(0.0f);

#pragma unroll
            for (int cc = 0; cc < 8; ++cc) {
                const int c = cb + cc;
                uint4 A0 = *(const uint4*)&sA[c][ty * 16];
                uint4 A1 = *(const uint4*)&sA[c][ty * 16 + 8];
                uint4 Bv = *(const uint4*)&sB[c][tx * 8];
                __half2 a2[8], b2[4];
                a2[0] = *(__half2*)&A0.x; a2[1] = *(__half2*)&A0.y;
                a2[2] = *(__half2*)&A0.z; a2[3] = *(__half2*)&A0.w;
                a2[4] = *(__half2*)&A1.x; a2[5] = *(__half2*)&A1.y;
                a2[6] = *(__half2*)&A1.z; a2[7] = *(__half2*)&A1.w;
                b2[0] = *(__half2*)&Bv.x; b2[1] = *(__half2*)&Bv.y;
                b2[2] = *(__half2*)&Bv.z; b2[3] = *(__half2*)&Bv.w;
#pragma unroll
                for (int i = 0; i < 8; ++i) {
#pragma unroll
                    for (int jp = 0; jp < 4; ++jp) {
                        // fma.rn.relu.f16x2: 2 fma-pipe instrs per half2.
                        hacc[i] = __hadd2(hacc[i],
                                          __hfma2_relu(a2[i], b2[jp],
                                                       mab2[i][jp]));
                    }
                }
            }

            // promote block accumulators to fp32 (tree into 2 accs)
            __half2 h01 = __hadd2(hacc[0], hacc[1]);
            __half2 h23 = __hadd2(hacc[2], hacc[3]);
            __half2 h45 = __hadd2(hacc[4], hacc[5]);
            __half2 h67 = __hadd2(hacc[6], hacc[7]);
            __half2 hA  = __hadd2(h01, h23);   // <=128 terms: fp16-safe
            __half2 hB  = __hadd2(h45, h67);
            facc[0] += __low2float(hA) + __high2float(hA);
            facc[1] += __low2float(hB) + __high2float(hB);
        }

        // Deterministic block reduction into g_part[tIdx].
        float tsum = facc[0] + facc[1];
#pragma unroll
        for (int off = 16; off > 0; off >>= 1)
            tsum += __shfl_down_sync(0xFFFFFFFFu, tsum, off);

        __syncthreads();   // release sA before aliased wred use
        if ((tid & 31) == 0) wred[tid >> 5] = tsum;
        __syncthreads();
        if (tid == 0) {
            float s = 0.0f;
#pragma unroll
            for (int w = 0; w < 8; ++w) s += wred[w];
            g_part[tIdx] = s;
        }
        __syncthreads();   // wred consumed before next tile's staging
    }

    // ---------------- Completion: last CTA does the final reduce ------------
    if (tid == 0) {
        __threadfence();
        unsigned ticket = atomicAdd(&g_ctr, 1u);
        lastf[0] = (ticket == PCTA - 1) ? 1 : 0;
    }
    __syncthreads();

    if (lastf[0]) {
        // Fixed-order deterministic final reduce over all 2048 partials.
        double s = 0.0;
#pragma unroll
        for (int k = 0; k < NTILE / 256; ++k)
            s += (double)g_part[tid + k * 256];
#pragma unroll
        for (int off = 16; off > 0; off >>= 1)
            s += __shfl_down_sync(0xFFFFFFFFu, s, off);
        if ((tid & 31) == 0) dw[tid >> 5] = s;
        __syncthreads();
        if (tid == 0) {
            double tot = 0.0;
#pragma unroll
            for (int w = 0; w < 8; ++w) tot += dw[w];
            out[0] = (float)(tot / (double)(R_ * B_));
            g_ctr  = 0;    // reset for next graph replay
            g_bar1 = 0;
        }
    }
}

extern "C" void kernel_launch(void* const* d_in, const int* in_sizes, int n_in,
                              void* d_out, int out_size) {
    const float* logits = (const float*)d_in[0];
    const int*   masks  = (const int*)d_in[1];
    float*       out    = (float*)d_out;

    fused_kernel<<<PCTA, 256>>>(logits, masks, out);
}